// round 13
// baseline (speedup 1.0000x reference)
#include <cuda_runtime.h>
#include <cstdint>

#define DIMC 256
#define NPIX 4096
#define BATCH 16
#define HID 512
#define NH 8
#define DH 64
#define KS 8                  // SYRK split-K slices

#define BK 32
#define LROW4 36              // 32 + 4 pad fp32 (144B row)
#define TILE4B (128 * LROW4 * 4)    // 18432 B
#define STAGEB (2 * TILE4B)   // 36864 B
#define NSTG 4
#define SMEMB (NSTG * STAGEB) // 147456 B

// ---------------- scratch (device globals, all fp32 rna-rounded) ----------------
__device__ float g_Gp [KS * BATCH * DIMC * DIMC];
__device__ float g_Xr [BATCH * DIMC * NPIX];    // rna(x), [b][c][n]
__device__ float g_XTr[BATCH * NPIX * DIMC];    // rna(x) transposed, [b][n][c]
__device__ float g_Gr [BATCH * DIMC * DIMC];    // G (rna)
__device__ float g_Pr [BATCH * HID * DIMC];     // P = Wk@G (rna)
__device__ float g_CTr[BATCH * NH * DH * DH];   // C^T [bh][e][d] (rna)
__device__ float g_MTr[BATCH * DIMC * HID];     // M^T [b][c][j] (rna)
__device__ float g_A  [BATCH * DIMC * DIMC];    // A_b (rna)
__device__ float g_Wr [3 * HID * DIMC];         // rna(w_qkv)
__device__ float g_WOr[DIMC * HID];             // rna(w_out)
__device__ float g_WqTr[NH * DIMC * DH];        // rna(Wq^T / 8) [h][c][d]

// ---------------- helpers ----------------
__device__ __forceinline__ float rna_tf32(float v) {
    uint32_t r;
    asm("cvt.rna.tf32.f32 %0, %1;" : "=r"(r) : "f"(v));
    return __uint_as_float(r);
}
__device__ __forceinline__ uint32_t smem_u32(const void* p) {
    uint32_t a;
    asm("{ .reg .u64 t; cvta.to.shared.u64 t, %1; cvt.u32.u64 %0, t; }" : "=r"(a) : "l"(p));
    return a;
}
__device__ __forceinline__ void cp16(uint32_t dst, const void* src) {
    asm volatile("cp.async.cg.shared.global [%0], [%1], 16;" :: "r"(dst), "l"(src));
}
#define CP_COMMIT() asm volatile("cp.async.commit_group;" ::: "memory")
#define CP_WAIT2()  asm volatile("cp.async.wait_group 2;" ::: "memory")

#define LDSM4(r0, r1, r2, r3, a) \
    asm volatile("ldmatrix.sync.aligned.m8n8.x4.shared.b16 {%0,%1,%2,%3}, [%4];" \
                 : "=r"(r0), "=r"(r1), "=r"(r2), "=r"(r3) : "r"(a))

__device__ __forceinline__ void mma1688t(float c[4],
                                         uint32_t a0, uint32_t a1, uint32_t a2, uint32_t a3,
                                         uint32_t b0, uint32_t b1) {
    asm volatile(
        "mma.sync.aligned.m16n8k8.row.col.f32.tf32.tf32.f32 "
        "{%0,%1,%2,%3},{%4,%5,%6,%7},{%8,%9},{%0,%1,%2,%3};"
        : "+f"(c[0]), "+f"(c[1]), "+f"(c[2]), "+f"(c[3])
        : "r"(a0), "r"(a1), "r"(a2), "r"(a3), "r"(b0), "r"(b1));
}

// ---------------- transforms ----------------
// x fp32 -> rna-rounded Xr (same layout) + XTr (transposed)
__global__ void transform_x(const float* __restrict__ x) {
    __shared__ float tile[32][33];
    int b = blockIdx.z, c0 = blockIdx.y * 32, n0 = blockIdx.x * 32;
    int tx = threadIdx.x, ty = threadIdx.y;   // 32 x 8
    const float* xb = x + (size_t)b * DIMC * NPIX;
    #pragma unroll
    for (int i = 0; i < 4; ++i) {
        int c = c0 + ty + i * 8, n = n0 + tx;
        float r = rna_tf32(xb[(size_t)c * NPIX + n]);
        tile[ty + i * 8][tx] = r;
        g_Xr[(size_t)b * DIMC * NPIX + (size_t)c * NPIX + n] = r;
    }
    __syncthreads();
    #pragma unroll
    for (int i = 0; i < 4; ++i) {
        int n = n0 + ty + i * 8, c = c0 + tx;
        g_XTr[(size_t)b * NPIX * DIMC + (size_t)n * DIMC + c] = tile[tx][ty + i * 8];
    }
}

__global__ void wsplit(const float* __restrict__ w_qkv, const float* __restrict__ w_out) {
    int idx = blockIdx.x * 256 + threadIdx.x;
    if (idx < 3 * HID * DIMC) g_Wr[idx] = rna_tf32(w_qkv[idx]);
    if (idx < DIMC * HID)     g_WOr[idx] = rna_tf32(w_out[idx]);
    if (idx < NH * DIMC * DH) {
        int d = idx & 63, c = (idx >> 6) & 255, h = idx >> 14;
        g_WqTr[idx] = rna_tf32(0.125f * w_qkv[(size_t)(h * 64 + d) * DIMC + c]);
    }
}

__global__ void reduce_g() {
    int idx = blockIdx.x * 256 + threadIdx.x;          // 262144 float4s
    const size_t S4 = (size_t)BATCH * DIMC * DIMC / 4;
    const float4* p = (const float4*)g_Gp;
    float4 v = p[idx];
    #pragma unroll
    for (int s = 1; s < KS; ++s) {
        float4 t = p[idx + s * S4];
        v.x += t.x; v.y += t.y; v.z += t.z; v.w += t.w;
    }
    float4 r = {rna_tf32(v.x), rna_tf32(v.y), rna_tf32(v.z), rna_tf32(v.w)};
    ((float4*)g_Gr)[idx] = r;
}

// ---------------- modes ----------------
#define MODE_SYRK  0
#define MODE_S1    1
#define MODE_S2    2
#define MODE_S3    3
#define MODE_S4    4
#define MODE_FINAL 5

#define EP_F32    0
#define EP_BIAS   1
#define EP_F32R   2
#define EP_F32R_T 3

__global__ void __launch_bounds__(512)
mma_kernel(int mode, const float* __restrict__ b_out, float* __restrict__ out)
{
    extern __shared__ char sm[];
    const int tid = threadIdx.x;
    const int lane = tid & 31, wid = tid >> 5;
    const int m0 = (wid >> 2) * 32, n0 = (wid & 3) * 32;   // 4x4 warps, 32x32 tiles
    const int bx = blockIdx.x;

    // ---- decode job ----
    const float *Af, *Bf;
    int lda, ldb, K, Ar = 128, Br = 128;
    int ep, orows = 128, ocols = 128, ldo;
    const float* bias = nullptr;
    float* eo32 = nullptr;
    float* em = nullptr;

    if (mode == MODE_SYRK) {
        int p = bx % 3, ks = (bx / 3) & (KS - 1), b = bx / (3 * KS);
        int ti = (p == 2) ? 1 : 0;
        int tj = (p == 0) ? 0 : 1;
        size_t ao = ((size_t)b * DIMC + ti * 128) * NPIX + (size_t)ks * (NPIX / KS);
        size_t bo = ((size_t)b * DIMC + tj * 128) * NPIX + (size_t)ks * (NPIX / KS);
        Af = g_Xr + ao; Bf = g_Xr + bo;
        lda = NPIX; ldb = NPIX; K = NPIX / KS;
        ep = EP_F32; ldo = DIMC;
        float* Gp = g_Gp + ((size_t)ks * BATCH + b) * DIMC * DIMC;
        eo32 = Gp + (size_t)ti * 128 * DIMC + tj * 128;
        if (ti != tj) em = Gp + (size_t)tj * 128 * DIMC + ti * 128;
    } else if (mode == MODE_S1) {
        int mt = bx & 3, nt = (bx >> 2) & 1, b = bx >> 3;
        Af = g_Wr + (size_t)(HID + mt * 128) * DIMC;                 // Wk rows
        Bf = g_Gr + (size_t)b * DIMC * DIMC + (size_t)nt * 128 * DIMC;  // G symmetric
        lda = DIMC; ldb = DIMC; K = DIMC;
        ep = EP_F32R; ldo = DIMC;
        eo32 = g_Pr + (size_t)b * HID * DIMC + (size_t)mt * 128 * DIMC + nt * 128;
    } else if (mode == MODE_S2) {
        int h = bx & 7, b = bx >> 3;
        Af = g_Pr + (size_t)b * HID * DIMC + (size_t)h * 64 * DIMC;
        Bf = g_Wr + (size_t)(2 * HID + h * 64) * DIMC;               // Wv rows
        lda = DIMC; ldb = DIMC; K = DIMC; Ar = 64; Br = 64;
        ep = EP_F32R_T; orows = 64; ocols = 64; ldo = 64;
        eo32 = g_CTr + (size_t)bx * DH * DH;                          // CT[e][d]
    } else if (mode == MODE_S3) {
        int nt = bx & 1, bh = bx >> 1, h = bh & 7, b = bh >> 3;
        Af = g_CTr + (size_t)bh * DH * DH;                            // CT[e][d] K-contig
        Bf = g_WqTr + (size_t)h * DIMC * DH + (size_t)nt * 128 * DH;  // WqT[c][d]
        lda = DH; ldb = DH; K = DH; Ar = 64; Br = 128;
        ep = EP_F32R_T; orows = 64; ocols = 128; ldo = HID;
        eo32 = g_MTr + (size_t)b * DIMC * HID + (size_t)nt * 128 * HID + h * 64;
    } else if (mode == MODE_S4) {
        int nt = bx & 1, mt = (bx >> 1) & 1, b = bx >> 2;
        Af = g_WOr + (size_t)mt * 128 * HID;
        Bf = g_MTr + (size_t)b * DIMC * HID + (size_t)nt * 128 * HID; // MT[c][j]
        lda = HID; ldb = HID; K = HID;
        ep = EP_F32R; ldo = DIMC;
        eo32 = g_A + (size_t)b * DIMC * DIMC + (size_t)mt * 128 * DIMC + nt * 128;
    } else {  // MODE_FINAL
        int mt = bx & 1, nt = (bx >> 1) & 31, b = bx >> 6;
        Af = g_A + (size_t)b * DIMC * DIMC + (size_t)mt * 128 * DIMC;
        Bf = g_XTr + (size_t)b * NPIX * DIMC + (size_t)nt * 128 * DIMC;
        lda = DIMC; ldb = DIMC; K = DIMC;
        ep = EP_BIAS; ldo = NPIX;
        bias = b_out + mt * 128;
        eo32 = out + (size_t)b * DIMC * NPIX + (size_t)mt * 128 * NPIX + nt * 128;
    }

    const uint32_t sbase = smem_u32(sm);
    const int nch = K >> 5;

    auto issue = [&](int c) {
        if (c < nch) {
            uint32_t stg = sbase + (uint32_t)(c & (NSTG - 1)) * STAGEB;
            int k0 = c * BK;
            #pragma unroll
            for (int i = 0; i < 2; ++i) {
                int u = tid + i * 512;
                int row = u >> 3, q = u & 7;
                int ra = row < Ar ? row : 0;
                int rb = row < Br ? row : 0;
                uint32_t d = stg + (uint32_t)(row * LROW4 + q * 4) * 4;
                cp16(d,          Af + (size_t)ra * lda + k0 + q * 4);
                cp16(d + TILE4B, Bf + (size_t)rb * ldb + k0 + q * 4);
            }
        }
        CP_COMMIT();
    };

    float acc[2][4][4];
    #pragma unroll
    for (int a = 0; a < 2; ++a)
        #pragma unroll
        for (int b2 = 0; b2 < 4; ++b2)
            #pragma unroll
            for (int c = 0; c < 4; ++c) acc[a][b2][c] = 0.0f;

    // tf32 fragment loads via b16 ldmatrix: lane group g = lane>>3, row r = lane&7
    const int lg = lane >> 3, lr = lane & 7;
    const uint32_t laneA4 = (uint32_t)((((lg & 1) * 8 + lr) * LROW4 + (lg >> 1) * 4) * 4);
    const uint32_t laneB4 = (uint32_t)((((lg >> 1) * 8 + lr) * LROW4 + (lg & 1) * 4) * 4);

    issue(0); issue(1); issue(2);

    for (int c = 0; c < nch; ++c) {
        CP_WAIT2();
        __syncthreads();
        issue(c + NSTG - 1);

        const uint32_t stg = sbase + (uint32_t)(c & (NSTG - 1)) * STAGEB;
        #pragma unroll
        for (int ks = 0; ks < 4; ++ks) {
            uint32_t a[2][4];
            #pragma unroll
            for (int mi = 0; mi < 2; ++mi)
                LDSM4(a[mi][0], a[mi][1], a[mi][2], a[mi][3],
                      stg + (uint32_t)(((m0 + mi * 16) * LROW4 + ks * 8) * 4) + laneA4);
            #pragma unroll
            for (int np = 0; np < 2; ++np) {
                uint32_t b0, b1, b2, b3;
                LDSM4(b0, b1, b2, b3,
                      stg + TILE4B + (uint32_t)(((n0 + np * 16) * LROW4 + ks * 8) * 4) + laneB4);
                #pragma unroll
                for (int mi = 0; mi < 2; ++mi) {
                    mma1688t(acc[mi][2*np],   a[mi][0], a[mi][1], a[mi][2], a[mi][3], b0, b1);
                    mma1688t(acc[mi][2*np+1], a[mi][0], a[mi][1], a[mi][2], a[mi][3], b2, b3);
                }
            }
        }
    }

    // ---- epilogue ----
    const int gr = lane >> 2, gc = (lane & 3) * 2;
    #pragma unroll
    for (int mi = 0; mi < 2; ++mi) {
        #pragma unroll
        for (int ni = 0; ni < 4; ++ni) {
            int r = m0 + mi * 16 + gr;
            int c = n0 + ni * 8 + gc;
            if (r >= orows || c >= ocols) continue;
            float v0 = acc[mi][ni][0], v1 = acc[mi][ni][1];
            float v2 = acc[mi][ni][2], v3 = acc[mi][ni][3];
            if (ep == EP_BIAS) {
                float bl = bias[r], bh = bias[r + 8];
                v0 += bl; v1 += bl; v2 += bh; v3 += bh;
            }
            if (ep == EP_F32 || ep == EP_BIAS) {
                float2 p0 = {v0, v1}, p1 = {v2, v3};
                *(float2*)&eo32[(size_t)r * ldo + c] = p0;
                *(float2*)&eo32[(size_t)(r + 8) * ldo + c] = p1;
                if (em) {
                    em[(size_t)c * ldo + r] = v0;
                    em[(size_t)(c + 1) * ldo + r] = v1;
                    em[(size_t)c * ldo + r + 8] = v2;
                    em[(size_t)(c + 1) * ldo + r + 8] = v3;
                }
            } else if (ep == EP_F32R) {
                float2 p0 = {rna_tf32(v0), rna_tf32(v1)};
                float2 p1 = {rna_tf32(v2), rna_tf32(v3)};
                *(float2*)&eo32[(size_t)r * ldo + c] = p0;
                *(float2*)&eo32[(size_t)(r + 8) * ldo + c] = p1;
            } else {   // EP_F32R_T : rna + transposed store [col][row]
                eo32[(size_t)c * ldo + r]           = rna_tf32(v0);
                eo32[(size_t)(c + 1) * ldo + r]     = rna_tf32(v1);
                eo32[(size_t)c * ldo + r + 8]       = rna_tf32(v2);
                eo32[(size_t)(c + 1) * ldo + r + 8] = rna_tf32(v3);
            }
        }
    }
}

// ---------------- launch ----------------
extern "C" void kernel_launch(void* const* d_in, const int* in_sizes, int n_in,
                              void* d_out, int out_size)
{
    const float* x     = (const float*)d_in[0];
    const float* w_qkv = (const float*)d_in[1];
    const float* w_out = (const float*)d_in[2];
    const float* b_out = (const float*)d_in[3];
    float* out = (float*)d_out;

    cudaFuncSetAttribute(mma_kernel, cudaFuncAttributeMaxDynamicSharedMemorySize, SMEMB);

    transform_x<<<dim3(128, 8, 16), dim3(32, 8)>>>(x);
    wsplit<<<1536, 256>>>(w_qkv, w_out);
    mma_kernel<<<3 * KS * 16, 512, SMEMB>>>(MODE_SYRK, b_out, out);
    reduce_g<<<1024, 256>>>();
    mma_kernel<<<128,  512, SMEMB>>>(MODE_S1,    b_out, out);
    mma_kernel<<<128,  512, SMEMB>>>(MODE_S2,    b_out, out);
    mma_kernel<<<256,  512, SMEMB>>>(MODE_S3,    b_out, out);
    mma_kernel<<<64,   512, SMEMB>>>(MODE_S4,    b_out, out);
    mma_kernel<<<1024, 512, SMEMB>>>(MODE_FINAL, b_out, out);
}